// round 15
// baseline (speedup 1.0000x reference)
#include <cuda_runtime.h>
#include <cuda_bf16.h>
#include <stdint.h>

#define M_PAIRS 4096
#define T_LEN   512
#define D_DIM   512
#define N_CAND  65
#define SPAN    4094u

// Device scratch (no allocations). Zero-init at load; counters self-reset.
__device__ __nv_bfloat16 g_enc [M_PAIRS * D_DIM];
__device__ float         g_pred[M_PAIRS * D_DIM];
__device__ int           g_sel [M_PAIRS * N_CAND];
__device__ float         g_rowloss[M_PAIRS];
__device__ float         g_rowacc [M_PAIRS];
__device__ unsigned int  g_cnt1[64];
__device__ unsigned int  g_cnt2;

// ---------------- Threefry-2x32 (20 rounds), exact JAX semantics ------------
struct TFK { uint32_t a, b; };

__host__ __device__ constexpr TFK tf2x32_c(uint32_t k0, uint32_t k1,
                                           uint32_t x0, uint32_t x1) {
    uint32_t ks2 = 0x1BD11BDAu ^ k0 ^ k1;
    x0 += k0; x1 += k1;
#define TF_RND(R) { x0 += x1; x1 = (x1 << (R)) | (x1 >> (32 - (R))); x1 ^= x0; }
    TF_RND(13) TF_RND(15) TF_RND(26) TF_RND(6)
    x0 += k1;  x1 += ks2 + 1u;
    TF_RND(17) TF_RND(29) TF_RND(16) TF_RND(24)
    x0 += ks2; x1 += k0 + 2u;
    TF_RND(13) TF_RND(15) TF_RND(26) TF_RND(6)
    x0 += k0;  x1 += k1 + 3u;
    TF_RND(17) TF_RND(29) TF_RND(16) TF_RND(24)
    x0 += k1;  x1 += ks2 + 4u;
    TF_RND(13) TF_RND(15) TF_RND(26) TF_RND(6)
    x0 += ks2; x1 += k0 + 5u;
#undef TF_RND
    return TFK{x0, x1};
}

__device__ constexpr TFK SK1 = tf2x32_c(0u, 42u, 0u, 0u);  // split(key(42))[0]
__device__ constexpr TFK SK2 = tf2x32_c(0u, 42u, 0u, 1u);  // split(key(42))[1]

__device__ __forceinline__ int tf_negative(int m, int n, int is64) {
    uint32_t t = (uint32_t)m * 64u + (uint32_t)n;
    TFK A = tf2x32_c(SK1.a, SK1.b, 0u, t);
    TFK B = tf2x32_c(SK2.a, SK2.b, 0u, t);
    uint32_t r;
    if (!is64) {
        uint32_t hi = A.a ^ A.b, lo = B.a ^ B.b;
        r = ((hi % SPAN) * 1024u + (lo % SPAN)) % SPAN;
    } else {
        unsigned long long hi = (((unsigned long long)A.a) << 32) | A.b;
        unsigned long long lo = (((unsigned long long)B.a) << 32) | B.b;
        r = (uint32_t)(((hi % 4094ull) * 512ull + (lo % 4094ull)) % 4094ull);
    }
    return (int)r + (((int)r >= m) ? 1 : 0);
}

// ---------------- packed f32x2 helpers ---------------------------------------
__device__ __forceinline__ void bfma2(unsigned long long& acc, uint32_t u,
                                      unsigned long long p2) {
    asm("{\n\t"
        ".reg .b32 lo, hi;\n\t"
        ".reg .b64 e;\n\t"
        "shl.b32 lo, %1, 16;\n\t"
        "and.b32 hi, %1, 0xFFFF0000;\n\t"
        "mov.b64 e, {lo, hi};\n\t"
        "fma.rn.f32x2 %0, e, %2, %0;\n\t"
        "}" : "+l"(acc) : "r"(u), "l"(p2));
}
__device__ __forceinline__ unsigned long long packf2(float lo, float hi) {
    unsigned long long r;
    asm("mov.b64 %0, {%1, %2};" : "=l"(r) : "f"(lo), "f"(hi));
    return r;
}
__device__ __forceinline__ float hadd2(unsigned long long a) {
    float lo, hi;
    asm("mov.b64 {%0, %1}, %2;" : "=f"(lo), "=f"(hi) : "l"(a));
    return lo + hi;
}

// ---- L1-bypassing 16B load --------------------------------------------------
__device__ __forceinline__ uint4 ldg_na(const void* p) {
    uint4 v;
    asm volatile("ld.global.nc.L1::no_allocate.v4.u32 {%0,%1,%2,%3}, [%4];"
                 : "=r"(v.x), "=r"(v.y), "=r"(v.z), "=r"(v.w) : "l"(p));
    return v;
}

__device__ __forceinline__ float dot8(uint4 v0, uint4 v1,
                                      const unsigned long long p2[8]) {
    unsigned long long acc = 0ull;
    bfma2(acc, v0.x, p2[0]);  bfma2(acc, v0.y, p2[1]);
    bfma2(acc, v0.z, p2[2]);  bfma2(acc, v0.w, p2[3]);
    bfma2(acc, v1.x, p2[4]);  bfma2(acc, v1.y, p2[5]);
    bfma2(acc, v1.z, p2[6]);  bfma2(acc, v1.w, p2[7]);
    return hadd2(acc);
}

// ---------------- Kernel 1: warp-per-row gather + norm + threefry -----------
__global__ void __launch_bounds__(256)
gather_norm_kernel(const float* __restrict__ pred,
                   const float* __restrict__ enc,
                   const void*  __restrict__ mask) {
    const int tid  = threadIdx.x;
    const int warp = tid >> 5, lane = tid & 31;
    const int m    = blockIdx.x * 8 + warp;
    const unsigned FULL = 0xFFFFFFFFu;

    int4 pw = ((const int4*)mask)[lane];
    unsigned any = __ballot_sync(FULL, (pw.y | pw.w) != 0);
    const int is64 = (any == 0u) ? 1 : 0;

    long long row, col;
    if (is64) {
        const long long* mm = (const long long*)mask;
        row = mm[2 * m]; col = mm[2 * m + 1];
    } else {
        const int* mm = (const int*)mask;
        row = mm[2 * m]; col = mm[2 * m + 1];
    }
    long long base = (row * (long long)T_LEN + col) * (long long)D_DIM;

    const float4* se = (const float4*)(enc  + base);
    const float4* sp = (const float4*)(pred + base);
    float4 e[4], p[4];
    #pragma unroll
    for (int j = 0; j < 4; j++) e[j] = se[lane + 32 * j];
    #pragma unroll
    for (int j = 0; j < 4; j++) p[j] = sp[lane + 32 * j];

    int n0 = tf_negative(m, 2 * lane,     is64);
    int n1 = tf_negative(m, 2 * lane + 1, is64);
    g_sel[m * N_CAND + 1 + 2 * lane] = n0;
    g_sel[m * N_CAND + 2 + 2 * lane] = n1;
    if (lane == 0) g_sel[m * N_CAND] = m;

    float sse = 0.0f, ssp = 0.0f;
    #pragma unroll
    for (int j = 0; j < 4; j++) {
        sse += e[j].x*e[j].x + e[j].y*e[j].y + e[j].z*e[j].z + e[j].w*e[j].w;
        ssp += p[j].x*p[j].x + p[j].y*p[j].y + p[j].z*p[j].z + p[j].w*p[j].w;
    }
    #pragma unroll
    for (int o = 16; o; o >>= 1) {
        sse += __shfl_xor_sync(FULL, sse, o);
        ssp += __shfl_xor_sync(FULL, ssp, o);
    }
    float invE = 1.0f / fmaxf(sqrtf(sse), 1e-12f);
    float invP = 1.0f / fmaxf(sqrtf(ssp), 1e-12f);

    uint2*  de = (uint2*)(g_enc  + (size_t)m * D_DIM);
    float4* dp = (float4*)(g_pred + (size_t)m * D_DIM);
    #pragma unroll
    for (int j = 0; j < 4; j++) {
        __nv_bfloat162 b0 = __floats2bfloat162_rn(e[j].x * invE, e[j].y * invE);
        __nv_bfloat162 b1 = __floats2bfloat162_rn(e[j].z * invE, e[j].w * invE);
        de[lane + 32 * j] = make_uint2(*reinterpret_cast<uint32_t*>(&b0),
                                       *reinterpret_cast<uint32_t*>(&b1));
        dp[lane + 32 * j] = make_float4(p[j].x * invP, p[j].y * invP,
                                        p[j].z * invP, p[j].w * invP);
    }
}

// ---------------- Kernel 2: sims, depth-3 load pipeline + batched reduce ----
__global__ void __launch_bounds__(256)
sim_kernel(float* __restrict__ out, int out_size) {
    int m    = blockIdx.x;
    int tid  = threadIdx.x;
    int warp = tid >> 5, lane = tid & 31;
    const unsigned FULL = 0xFFFFFFFFu;

    __shared__ int   sel[N_CAND];
    __shared__ float sims[N_CAND];
    __shared__ bool  last;

    if (tid < N_CAND) sel[tid] = g_sel[m * N_CAND + tid];

    // lane's 16 pred elements as 8 packed f32x2
    unsigned long long p2[8];
    {
        const float4* p4 = (const float4*)(g_pred + (size_t)m * D_DIM);
        #pragma unroll
        for (int j = 0; j < 2; j++) {
            float4 a = p4[j * 64 + lane * 2];
            float4 b = p4[j * 64 + lane * 2 + 1];
            p2[j*4 + 0] = packf2(a.x, a.y);
            p2[j*4 + 1] = packf2(a.z, a.w);
            p2[j*4 + 2] = packf2(b.x, b.y);
            p2[j*4 + 3] = packf2(b.z, b.w);
        }
    }
    __syncthreads();

    // ---- warp w: candidates w+8j (j=0..7), 3 rows in flight ----
    const char* ebase = (const char*)g_enc;
    float d[8];
    uint4 A[3], B[3];
    uint4 t0, t1;                       // tail candidate 64 (warp 0), early issue
    {
        const char* r0 = ebase + (size_t)sel[warp]     * 1024;
        const char* r1 = ebase + (size_t)sel[warp + 8] * 1024;
        A[0] = ldg_na(r0 + lane * 16);  B[0] = ldg_na(r0 + 512 + lane * 16);
        A[1] = ldg_na(r1 + lane * 16);  B[1] = ldg_na(r1 + 512 + lane * 16);
        if (warp == 0) {
            const char* rt = ebase + (size_t)sel[64] * 1024;
            t0 = ldg_na(rt + lane * 16);
            t1 = ldg_na(rt + 512 + lane * 16);
        }
        #pragma unroll
        for (int j = 0; j < 8; j++) {
            if (j < 6) {   // producer writes stage (j+2)%3 == stage freed at j-1
                const char* rn = ebase + (size_t)sel[warp + 8 * (j + 2)] * 1024;
                A[(j + 2) % 3] = ldg_na(rn + lane * 16);
                B[(j + 2) % 3] = ldg_na(rn + 512 + lane * 16);
            }
            d[j] = dot8(A[j % 3], B[j % 3], p2);
        }
    }

    // ---- fold-butterfly: 8 candidates reduced with 9 SHFLs ----
    {
        float e[4], f[2], g;
        #pragma unroll
        for (int k = 0; k < 4; k++) {
            float v = (lane & 1) ? d[2*k+1] : d[2*k];
            float w = (lane & 1) ? d[2*k]   : d[2*k+1];
            e[k] = v + __shfl_xor_sync(FULL, w, 1);
        }
        #pragma unroll
        for (int k = 0; k < 2; k++) {
            float v = (lane & 2) ? e[2*k+1] : e[2*k];
            float w = (lane & 2) ? e[2*k]   : e[2*k+1];
            f[k] = v + __shfl_xor_sync(FULL, w, 2);
        }
        {
            float v = (lane & 4) ? f[1] : f[0];
            float w = (lane & 4) ? f[0] : f[1];
            g = v + __shfl_xor_sync(FULL, w, 4);
        }
        g += __shfl_xor_sync(FULL, g, 8);
        g += __shfl_xor_sync(FULL, g, 16);
        if (lane < 8) sims[warp + 8 * lane] = g * 10.0f;
    }

    // tail candidate 64 (warp 0, data already in flight)
    if (warp == 0) {
        float dt = dot8(t0, t1, p2);
        #pragma unroll
        for (int o = 16; o; o >>= 1) dt += __shfl_xor_sync(FULL, dt, o);
        if (lane == 0) sims[64] = dt * 10.0f;
    }
    __syncthreads();

    // ---- warp-parallel LSE / argmax (warp 0) ----
    if (warp == 0) {
        float v0 = sims[lane];
        float v1 = sims[lane + 32];
        float v2 = (lane == 0) ? sims[64] : -3.4e38f;
        float mx = fmaxf(fmaxf(v0, v1), v2);
        #pragma unroll
        for (int o = 16; o; o >>= 1) mx = fmaxf(mx, __shfl_xor_sync(FULL, mx, o));
        float s = expf(v0 - mx) + expf(v1 - mx) + ((lane == 0) ? expf(v2 - mx) : 0.0f);
        #pragma unroll
        for (int o = 16; o; o >>= 1) s += __shfl_xor_sync(FULL, s, o);
        if (lane == 0) {
            float s0 = sims[0];
            g_rowloss[m] = mx + logf(s) - s0;
            g_rowacc[m]  = (s0 >= mx) ? 1.0f : 0.0f;
        }
    }

    // ---- two-level arrival tree + fused deterministic final reduce ----
    __syncthreads();
    __threadfence();
    if (tid == 0) {
        bool l = false;
        if (atomicAdd(&g_cnt1[m >> 6], 1u) == 63u) {
            if (atomicAdd(&g_cnt2, 1u) == 63u) l = true;
        }
        last = l;
    }
    __syncthreads();
    if (!last) return;
    __threadfence();

    if (tid < 64) g_cnt1[tid] = 0u;        // self-reset for next replay
    if (tid == 64) g_cnt2 = 0u;

    float sl = 0.0f, sa = 0.0f;
    #pragma unroll
    for (int k = 0; k < M_PAIRS / 256; k++) {
        int i = k * 256 + tid;
        sl += g_rowloss[i];
        sa += g_rowacc[i];
    }
    __shared__ float bl[8], ba[8];
    #pragma unroll
    for (int o = 16; o; o >>= 1) {
        sl += __shfl_xor_sync(FULL, sl, o);
        sa += __shfl_xor_sync(FULL, sa, o);
    }
    if (lane == 0) { bl[warp] = sl; ba[warp] = sa; }
    __syncthreads();
    if (tid == 0) {
        float tl = 0.0f, ta = 0.0f;
        #pragma unroll
        for (int w = 0; w < 8; w++) { tl += bl[w]; ta += ba[w]; }
        out[0] = tl / (float)M_PAIRS;
        if (out_size > 1) out[1] = ta / (float)M_PAIRS;
    }
}

// ---------------- Launch ----------------------------------------------------
extern "C" void kernel_launch(void* const* d_in, const int* in_sizes, int n_in,
                              void* d_out, int out_size) {
    const float* pred = (const float*)d_in[0];
    const float* enc  = (const float*)d_in[1];
    const void*  mask = d_in[2];

    gather_norm_kernel<<<M_PAIRS / 8, 256>>>(pred, enc, mask);
    sim_kernel<<<M_PAIRS, 256>>>((float*)d_out, out_size);
}

// round 16
// speedup vs baseline: 1.0544x; 1.0544x over previous
#include <cuda_runtime.h>
#include <cuda_bf16.h>
#include <stdint.h>

#define M_PAIRS 4096
#define T_LEN   512
#define D_DIM   512
#define N_CAND  65
#define SPAN    4094u

// Device scratch (no allocations). Zero-init at load; counters self-reset.
__device__ __nv_bfloat16 g_enc [M_PAIRS * D_DIM];
__device__ float         g_pred[M_PAIRS * D_DIM];
__device__ int           g_sel [M_PAIRS * N_CAND];
__device__ float         g_rowloss[M_PAIRS];
__device__ float         g_rowacc [M_PAIRS];
__device__ unsigned int  g_cnt1[64];
__device__ unsigned int  g_cnt2;

// ---------------- Threefry-2x32 (20 rounds), exact JAX semantics ------------
struct TFK { uint32_t a, b; };

__host__ __device__ constexpr TFK tf2x32_c(uint32_t k0, uint32_t k1,
                                           uint32_t x0, uint32_t x1) {
    uint32_t ks2 = 0x1BD11BDAu ^ k0 ^ k1;
    x0 += k0; x1 += k1;
#define TF_RND(R) { x0 += x1; x1 = (x1 << (R)) | (x1 >> (32 - (R))); x1 ^= x0; }
    TF_RND(13) TF_RND(15) TF_RND(26) TF_RND(6)
    x0 += k1;  x1 += ks2 + 1u;
    TF_RND(17) TF_RND(29) TF_RND(16) TF_RND(24)
    x0 += ks2; x1 += k0 + 2u;
    TF_RND(13) TF_RND(15) TF_RND(26) TF_RND(6)
    x0 += k0;  x1 += k1 + 3u;
    TF_RND(17) TF_RND(29) TF_RND(16) TF_RND(24)
    x0 += k1;  x1 += ks2 + 4u;
    TF_RND(13) TF_RND(15) TF_RND(26) TF_RND(6)
    x0 += ks2; x1 += k0 + 5u;
#undef TF_RND
    return TFK{x0, x1};
}

__device__ constexpr TFK SK1 = tf2x32_c(0u, 42u, 0u, 0u);  // split(key(42))[0]
__device__ constexpr TFK SK2 = tf2x32_c(0u, 42u, 0u, 1u);  // split(key(42))[1]

__device__ __forceinline__ int tf_negative(int m, int n, int is64) {
    uint32_t t = (uint32_t)m * 64u + (uint32_t)n;
    TFK A = tf2x32_c(SK1.a, SK1.b, 0u, t);
    TFK B = tf2x32_c(SK2.a, SK2.b, 0u, t);
    uint32_t r;
    if (!is64) {
        uint32_t hi = A.a ^ A.b, lo = B.a ^ B.b;
        r = ((hi % SPAN) * 1024u + (lo % SPAN)) % SPAN;
    } else {
        unsigned long long hi = (((unsigned long long)A.a) << 32) | A.b;
        unsigned long long lo = (((unsigned long long)B.a) << 32) | B.b;
        r = (uint32_t)(((hi % 4094ull) * 512ull + (lo % 4094ull)) % 4094ull);
    }
    return (int)r + (((int)r >= m) ? 1 : 0);
}

// ---------------- packed f32x2 helpers ---------------------------------------
__device__ __forceinline__ void bfma2(unsigned long long& acc, uint32_t u,
                                      unsigned long long p2) {
    asm("{\n\t"
        ".reg .b32 lo, hi;\n\t"
        ".reg .b64 e;\n\t"
        "shl.b32 lo, %1, 16;\n\t"
        "and.b32 hi, %1, 0xFFFF0000;\n\t"
        "mov.b64 e, {lo, hi};\n\t"
        "fma.rn.f32x2 %0, e, %2, %0;\n\t"
        "}" : "+l"(acc) : "r"(u), "l"(p2));
}
__device__ __forceinline__ unsigned long long packf2(float lo, float hi) {
    unsigned long long r;
    asm("mov.b64 %0, {%1, %2};" : "=l"(r) : "f"(lo), "f"(hi));
    return r;
}
__device__ __forceinline__ float hadd2(unsigned long long a) {
    float lo, hi;
    asm("mov.b64 {%0, %1}, %2;" : "=f"(lo), "=f"(hi) : "l"(a));
    return lo + hi;
}

// ---- L1-bypassing 16B load --------------------------------------------------
__device__ __forceinline__ uint4 ldg_na(const void* p) {
    uint4 v;
    asm volatile("ld.global.nc.L1::no_allocate.v4.u32 {%0,%1,%2,%3}, [%4];"
                 : "=r"(v.x), "=r"(v.y), "=r"(v.z), "=r"(v.w) : "l"(p));
    return v;
}

__device__ __forceinline__ float dot8(uint4 v0, uint4 v1,
                                      const unsigned long long p2[8]) {
    unsigned long long acc = 0ull;
    bfma2(acc, v0.x, p2[0]);  bfma2(acc, v0.y, p2[1]);
    bfma2(acc, v0.z, p2[2]);  bfma2(acc, v0.w, p2[3]);
    bfma2(acc, v1.x, p2[4]);  bfma2(acc, v1.y, p2[5]);
    bfma2(acc, v1.z, p2[6]);  bfma2(acc, v1.w, p2[7]);
    return hadd2(acc);
}

// ---------------- Kernel 1: warp-per-row gather + norm + threefry -----------
__global__ void __launch_bounds__(256)
gather_norm_kernel(const float* __restrict__ pred,
                   const float* __restrict__ enc,
                   const void*  __restrict__ mask) {
    const int tid  = threadIdx.x;
    const int warp = tid >> 5, lane = tid & 31;
    const int m    = blockIdx.x * 8 + warp;
    const unsigned FULL = 0xFFFFFFFFu;

    int4 pw = ((const int4*)mask)[lane];
    unsigned any = __ballot_sync(FULL, (pw.y | pw.w) != 0);
    const int is64 = (any == 0u) ? 1 : 0;

    long long row, col;
    if (is64) {
        const long long* mm = (const long long*)mask;
        row = mm[2 * m]; col = mm[2 * m + 1];
    } else {
        const int* mm = (const int*)mask;
        row = mm[2 * m]; col = mm[2 * m + 1];
    }
    long long base = (row * (long long)T_LEN + col) * (long long)D_DIM;

    const float4* se = (const float4*)(enc  + base);
    const float4* sp = (const float4*)(pred + base);
    float4 e[4], p[4];
    #pragma unroll
    for (int j = 0; j < 4; j++) e[j] = se[lane + 32 * j];
    #pragma unroll
    for (int j = 0; j < 4; j++) p[j] = sp[lane + 32 * j];

    int n0 = tf_negative(m, 2 * lane,     is64);
    int n1 = tf_negative(m, 2 * lane + 1, is64);
    g_sel[m * N_CAND + 1 + 2 * lane] = n0;
    g_sel[m * N_CAND + 2 + 2 * lane] = n1;
    if (lane == 0) g_sel[m * N_CAND] = m;

    float sse = 0.0f, ssp = 0.0f;
    #pragma unroll
    for (int j = 0; j < 4; j++) {
        sse += e[j].x*e[j].x + e[j].y*e[j].y + e[j].z*e[j].z + e[j].w*e[j].w;
        ssp += p[j].x*p[j].x + p[j].y*p[j].y + p[j].z*p[j].z + p[j].w*p[j].w;
    }
    #pragma unroll
    for (int o = 16; o; o >>= 1) {
        sse += __shfl_xor_sync(FULL, sse, o);
        ssp += __shfl_xor_sync(FULL, ssp, o);
    }
    float invE = 1.0f / fmaxf(sqrtf(sse), 1e-12f);
    float invP = 1.0f / fmaxf(sqrtf(ssp), 1e-12f);

    uint2*  de = (uint2*)(g_enc  + (size_t)m * D_DIM);
    float4* dp = (float4*)(g_pred + (size_t)m * D_DIM);
    #pragma unroll
    for (int j = 0; j < 4; j++) {
        __nv_bfloat162 b0 = __floats2bfloat162_rn(e[j].x * invE, e[j].y * invE);
        __nv_bfloat162 b1 = __floats2bfloat162_rn(e[j].z * invE, e[j].w * invE);
        de[lane + 32 * j] = make_uint2(*reinterpret_cast<uint32_t*>(&b0),
                                       *reinterpret_cast<uint32_t*>(&b1));
        dp[lane + 32 * j] = make_float4(p[j].x * invP, p[j].y * invP,
                                        p[j].z * invP, p[j].w * invP);
    }
}

// ---------------- Kernel 2: sims (R13 structure, reg-capped for 100% occ) ---
__global__ void __launch_bounds__(256, 8)
sim_kernel(float* __restrict__ out, int out_size) {
    int m    = blockIdx.x;
    int tid  = threadIdx.x;
    int warp = tid >> 5, lane = tid & 31;
    const unsigned FULL = 0xFFFFFFFFu;

    __shared__ int   sel[N_CAND];
    __shared__ float sims[N_CAND];
    __shared__ bool  last;

    if (tid < N_CAND) sel[tid] = g_sel[m * N_CAND + tid];

    // lane's 16 pred elements as 8 packed f32x2
    unsigned long long p2[8];
    {
        const float4* p4 = (const float4*)(g_pred + (size_t)m * D_DIM);
        #pragma unroll
        for (int j = 0; j < 2; j++) {
            float4 a = p4[j * 64 + lane * 2];
            float4 b = p4[j * 64 + lane * 2 + 1];
            p2[j*4 + 0] = packf2(a.x, a.y);
            p2[j*4 + 1] = packf2(a.z, a.w);
            p2[j*4 + 2] = packf2(b.x, b.y);
            p2[j*4 + 3] = packf2(b.z, b.w);
        }
    }
    __syncthreads();

    // ---- warp w: candidates w+8j (j=0..7), depth-2 load pipeline ----
    float d[8];
    {
        const char* b0p = (const char*)g_enc + (size_t)sel[warp] * 1024;
        uint4 a0 = ldg_na(b0p + lane * 16);
        uint4 a1 = ldg_na(b0p + 512 + lane * 16);
        #pragma unroll
        for (int j = 0; j < 8; j++) {
            uint4 n0, n1;
            if (j < 7) {
                const char* nb = (const char*)g_enc
                               + (size_t)sel[warp + 8 * (j + 1)] * 1024;
                n0 = ldg_na(nb + lane * 16);
                n1 = ldg_na(nb + 512 + lane * 16);
            }
            d[j] = dot8(a0, a1, p2);
            if (j < 7) { a0 = n0; a1 = n1; }
        }
    }

    // ---- fold-butterfly: 8 candidates reduced with 9 SHFLs ----
    {
        float e[4], f[2], g;
        #pragma unroll
        for (int k = 0; k < 4; k++) {
            float v = (lane & 1) ? d[2*k+1] : d[2*k];
            float w = (lane & 1) ? d[2*k]   : d[2*k+1];
            e[k] = v + __shfl_xor_sync(FULL, w, 1);
        }
        #pragma unroll
        for (int k = 0; k < 2; k++) {
            float v = (lane & 2) ? e[2*k+1] : e[2*k];
            float w = (lane & 2) ? e[2*k]   : e[2*k+1];
            f[k] = v + __shfl_xor_sync(FULL, w, 2);
        }
        {
            float v = (lane & 4) ? f[1] : f[0];
            float w = (lane & 4) ? f[0] : f[1];
            g = v + __shfl_xor_sync(FULL, w, 4);
        }
        g += __shfl_xor_sync(FULL, g, 8);
        g += __shfl_xor_sync(FULL, g, 16);
        if (lane < 8) sims[warp + 8 * lane] = g * 10.0f;
    }

    // tail candidate 64 (warp 0)
    if (warp == 0) {
        const char* eT = (const char*)g_enc + (size_t)sel[64] * 1024;
        uint4 t0 = ldg_na(eT + lane * 16);
        uint4 t1 = ldg_na(eT + 512 + lane * 16);
        float dt = dot8(t0, t1, p2);
        #pragma unroll
        for (int o = 16; o; o >>= 1) dt += __shfl_xor_sync(FULL, dt, o);
        if (lane == 0) sims[64] = dt * 10.0f;
    }
    __syncthreads();

    // ---- warp-parallel LSE / argmax (warp 0) ----
    if (warp == 0) {
        float v0 = sims[lane];
        float v1 = sims[lane + 32];
        float v2 = (lane == 0) ? sims[64] : -3.4e38f;
        float mx = fmaxf(fmaxf(v0, v1), v2);
        #pragma unroll
        for (int o = 16; o; o >>= 1) mx = fmaxf(mx, __shfl_xor_sync(FULL, mx, o));
        float s = expf(v0 - mx) + expf(v1 - mx) + ((lane == 0) ? expf(v2 - mx) : 0.0f);
        #pragma unroll
        for (int o = 16; o; o >>= 1) s += __shfl_xor_sync(FULL, s, o);
        if (lane == 0) {
            float s0 = sims[0];
            g_rowloss[m] = mx + logf(s) - s0;
            g_rowacc[m]  = (s0 >= mx) ? 1.0f : 0.0f;
        }
    }

    // ---- two-level arrival tree + fused deterministic final reduce ----
    __syncthreads();
    __threadfence();
    if (tid == 0) {
        bool l = false;
        if (atomicAdd(&g_cnt1[m >> 6], 1u) == 63u) {
            if (atomicAdd(&g_cnt2, 1u) == 63u) l = true;
        }
        last = l;
    }
    __syncthreads();
    if (!last) return;
    __threadfence();

    if (tid < 64) g_cnt1[tid] = 0u;        // self-reset for next replay
    if (tid == 64) g_cnt2 = 0u;

    float sl = 0.0f, sa = 0.0f;
    #pragma unroll
    for (int k = 0; k < M_PAIRS / 256; k++) {
        int i = k * 256 + tid;
        sl += g_rowloss[i];
        sa += g_rowacc[i];
    }
    __shared__ float bl[8], ba[8];
    #pragma unroll
    for (int o = 16; o; o >>= 1) {
        sl += __shfl_xor_sync(FULL, sl, o);
        sa += __shfl_xor_sync(FULL, sa, o);
    }
    if (lane == 0) { bl[warp] = sl; ba[warp] = sa; }
    __syncthreads();
    if (tid == 0) {
        float tl = 0.0f, ta = 0.0f;
        #pragma unroll
        for (int w = 0; w < 8; w++) { tl += bl[w]; ta += ba[w]; }
        out[0] = tl / (float)M_PAIRS;
        if (out_size > 1) out[1] = ta / (float)M_PAIRS;
    }
}

// ---------------- Launch ----------------------------------------------------
extern "C" void kernel_launch(void* const* d_in, const int* in_sizes, int n_in,
                              void* d_out, int out_size) {
    const float* pred = (const float*)d_in[0];
    const float* enc  = (const float*)d_in[1];
    const void*  mask = d_in[2];

    gather_norm_kernel<<<M_PAIRS / 8, 256>>>(pred, enc, mask);
    sim_kernel<<<M_PAIRS, 256>>>((float*)d_out, out_size);
}

// round 17
// speedup vs baseline: 1.0839x; 1.0280x over previous
#include <cuda_runtime.h>
#include <cuda_bf16.h>
#include <stdint.h>

#define M_PAIRS 4096
#define T_LEN   512
#define D_DIM   512
#define N_CAND  65
#define SPAN    4094u

// Device scratch (no allocations). Zero-init at load; counters self-reset.
__device__ __nv_bfloat16 g_enc [M_PAIRS * D_DIM];
__device__ float         g_pred[M_PAIRS * D_DIM];
__device__ int           g_sel [M_PAIRS * N_CAND];
__device__ float         g_rowloss[M_PAIRS];
__device__ float         g_rowacc [M_PAIRS];
__device__ unsigned int  g_cnt1[64];
__device__ unsigned int  g_cnt2;

// ---------------- Threefry-2x32 (20 rounds), exact JAX semantics ------------
struct TFK { uint32_t a, b; };

__host__ __device__ constexpr TFK tf2x32_c(uint32_t k0, uint32_t k1,
                                           uint32_t x0, uint32_t x1) {
    uint32_t ks2 = 0x1BD11BDAu ^ k0 ^ k1;
    x0 += k0; x1 += k1;
#define TF_RND(R) { x0 += x1; x1 = (x1 << (R)) | (x1 >> (32 - (R))); x1 ^= x0; }
    TF_RND(13) TF_RND(15) TF_RND(26) TF_RND(6)
    x0 += k1;  x1 += ks2 + 1u;
    TF_RND(17) TF_RND(29) TF_RND(16) TF_RND(24)
    x0 += ks2; x1 += k0 + 2u;
    TF_RND(13) TF_RND(15) TF_RND(26) TF_RND(6)
    x0 += k0;  x1 += k1 + 3u;
    TF_RND(17) TF_RND(29) TF_RND(16) TF_RND(24)
    x0 += k1;  x1 += ks2 + 4u;
    TF_RND(13) TF_RND(15) TF_RND(26) TF_RND(6)
    x0 += ks2; x1 += k0 + 5u;
#undef TF_RND
    return TFK{x0, x1};
}

__device__ constexpr TFK SK1 = tf2x32_c(0u, 42u, 0u, 0u);  // split(key(42))[0]
__device__ constexpr TFK SK2 = tf2x32_c(0u, 42u, 0u, 1u);  // split(key(42))[1]

__device__ __forceinline__ int tf_negative(int m, int n, int is64) {
    uint32_t t = (uint32_t)m * 64u + (uint32_t)n;
    TFK A = tf2x32_c(SK1.a, SK1.b, 0u, t);
    TFK B = tf2x32_c(SK2.a, SK2.b, 0u, t);
    uint32_t r;
    if (!is64) {
        uint32_t hi = A.a ^ A.b, lo = B.a ^ B.b;
        r = ((hi % SPAN) * 1024u + (lo % SPAN)) % SPAN;
    } else {
        unsigned long long hi = (((unsigned long long)A.a) << 32) | A.b;
        unsigned long long lo = (((unsigned long long)B.a) << 32) | B.b;
        r = (uint32_t)(((hi % 4094ull) * 512ull + (lo % 4094ull)) % 4094ull);
    }
    return (int)r + (((int)r >= m) ? 1 : 0);
}

// ---------------- packed f32x2 helpers ---------------------------------------
__device__ __forceinline__ void bfma2(unsigned long long& acc, uint32_t u,
                                      unsigned long long p2) {
    asm("{\n\t"
        ".reg .b32 lo, hi;\n\t"
        ".reg .b64 e;\n\t"
        "shl.b32 lo, %1, 16;\n\t"
        "and.b32 hi, %1, 0xFFFF0000;\n\t"
        "mov.b64 e, {lo, hi};\n\t"
        "fma.rn.f32x2 %0, e, %2, %0;\n\t"
        "}" : "+l"(acc) : "r"(u), "l"(p2));
}
__device__ __forceinline__ unsigned long long packf2(float lo, float hi) {
    unsigned long long r;
    asm("mov.b64 %0, {%1, %2};" : "=l"(r) : "f"(lo), "f"(hi));
    return r;
}
__device__ __forceinline__ float hadd2(unsigned long long a) {
    float lo, hi;
    asm("mov.b64 {%0, %1}, %2;" : "=f"(lo), "=f"(hi) : "l"(a));
    return lo + hi;
}

// ---- PDL controls ------------------------------------------------------------
__device__ __forceinline__ void gdc_launch_dependents() {
    asm volatile("griddepcontrol.launch_dependents;" ::: "memory");
}
__device__ __forceinline__ void gdc_wait() {
    asm volatile("griddepcontrol.wait;" ::: "memory");
}

// ---- L1-bypassing 16B load --------------------------------------------------
__device__ __forceinline__ uint4 ldg_na(const void* p) {
    uint4 v;
    asm volatile("ld.global.nc.L1::no_allocate.v4.u32 {%0,%1,%2,%3}, [%4];"
                 : "=r"(v.x), "=r"(v.y), "=r"(v.z), "=r"(v.w) : "l"(p));
    return v;
}

__device__ __forceinline__ float dot8(uint4 v0, uint4 v1,
                                      const unsigned long long p2[8]) {
    unsigned long long acc = 0ull;
    bfma2(acc, v0.x, p2[0]);  bfma2(acc, v0.y, p2[1]);
    bfma2(acc, v0.z, p2[2]);  bfma2(acc, v0.w, p2[3]);
    bfma2(acc, v1.x, p2[4]);  bfma2(acc, v1.y, p2[5]);
    bfma2(acc, v1.z, p2[6]);  bfma2(acc, v1.w, p2[7]);
    return hadd2(acc);
}

// ---------------- Kernel 1: warp-per-row gather + norm + threefry -----------
__global__ void __launch_bounds__(256)
gather_norm_kernel(const float* __restrict__ pred,
                   const float* __restrict__ enc,
                   const void*  __restrict__ mask) {
    const int tid  = threadIdx.x;
    const int warp = tid >> 5, lane = tid & 31;
    const int m    = blockIdx.x * 8 + warp;
    const unsigned FULL = 0xFFFFFFFFu;

    int4 pw = ((const int4*)mask)[lane];
    unsigned any = __ballot_sync(FULL, (pw.y | pw.w) != 0);
    const int is64 = (any == 0u) ? 1 : 0;

    long long row, col;
    if (is64) {
        const long long* mm = (const long long*)mask;
        row = mm[2 * m]; col = mm[2 * m + 1];
    } else {
        const int* mm = (const int*)mask;
        row = mm[2 * m]; col = mm[2 * m + 1];
    }
    long long base = (row * (long long)T_LEN + col) * (long long)D_DIM;

    const float4* se = (const float4*)(enc  + base);
    const float4* sp = (const float4*)(pred + base);
    float4 e[4], p[4];
    #pragma unroll
    for (int j = 0; j < 4; j++) e[j] = se[lane + 32 * j];
    #pragma unroll
    for (int j = 0; j < 4; j++) p[j] = sp[lane + 32 * j];

    int n0 = tf_negative(m, 2 * lane,     is64);
    int n1 = tf_negative(m, 2 * lane + 1, is64);
    g_sel[m * N_CAND + 1 + 2 * lane] = n0;
    g_sel[m * N_CAND + 2 + 2 * lane] = n1;
    if (lane == 0) g_sel[m * N_CAND] = m;

    float sse = 0.0f, ssp = 0.0f;
    #pragma unroll
    for (int j = 0; j < 4; j++) {
        sse += e[j].x*e[j].x + e[j].y*e[j].y + e[j].z*e[j].z + e[j].w*e[j].w;
        ssp += p[j].x*p[j].x + p[j].y*p[j].y + p[j].z*p[j].z + p[j].w*p[j].w;
    }
    #pragma unroll
    for (int o = 16; o; o >>= 1) {
        sse += __shfl_xor_sync(FULL, sse, o);
        ssp += __shfl_xor_sync(FULL, ssp, o);
    }
    float invE = 1.0f / fmaxf(sqrtf(sse), 1e-12f);
    float invP = 1.0f / fmaxf(sqrtf(ssp), 1e-12f);

    uint2*  de = (uint2*)(g_enc  + (size_t)m * D_DIM);
    float4* dp = (float4*)(g_pred + (size_t)m * D_DIM);
    #pragma unroll
    for (int j = 0; j < 4; j++) {
        __nv_bfloat162 b0 = __floats2bfloat162_rn(e[j].x * invE, e[j].y * invE);
        __nv_bfloat162 b1 = __floats2bfloat162_rn(e[j].z * invE, e[j].w * invE);
        de[lane + 32 * j] = make_uint2(*reinterpret_cast<uint32_t*>(&b0),
                                       *reinterpret_cast<uint32_t*>(&b1));
        dp[lane + 32 * j] = make_float4(p[j].x * invP, p[j].y * invP,
                                        p[j].z * invP, p[j].w * invP);
    }

    gdc_launch_dependents();   // allow sim_kernel to begin dispatch
}

// ---------------- Kernel 2: sims (exact R13 structure) + PDL wait -----------
__global__ void __launch_bounds__(256)
sim_kernel(float* __restrict__ out, int out_size) {
    int m    = blockIdx.x;
    int tid  = threadIdx.x;
    int warp = tid >> 5, lane = tid & 31;
    const unsigned FULL = 0xFFFFFFFFu;

    __shared__ int   sel[N_CAND];
    __shared__ float sims[N_CAND];
    __shared__ bool  last;

    gdc_wait();   // gather's stores visible from here

    if (tid < N_CAND) sel[tid] = g_sel[m * N_CAND + tid];

    // lane's 16 pred elements as 8 packed f32x2
    unsigned long long p2[8];
    {
        const float4* p4 = (const float4*)(g_pred + (size_t)m * D_DIM);
        #pragma unroll
        for (int j = 0; j < 2; j++) {
            float4 a = p4[j * 64 + lane * 2];
            float4 b = p4[j * 64 + lane * 2 + 1];
            p2[j*4 + 0] = packf2(a.x, a.y);
            p2[j*4 + 1] = packf2(a.z, a.w);
            p2[j*4 + 2] = packf2(b.x, b.y);
            p2[j*4 + 3] = packf2(b.z, b.w);
        }
    }
    __syncthreads();

    // ---- warp w: candidates w+8j (j=0..7), depth-2 load pipeline ----
    float d[8];
    {
        const char* b0p = (const char*)g_enc + (size_t)sel[warp] * 1024;
        uint4 a0 = ldg_na(b0p + lane * 16);
        uint4 a1 = ldg_na(b0p + 512 + lane * 16);
        #pragma unroll
        for (int j = 0; j < 8; j++) {
            uint4 n0, n1;
            if (j < 7) {
                const char* nb = (const char*)g_enc
                               + (size_t)sel[warp + 8 * (j + 1)] * 1024;
                n0 = ldg_na(nb + lane * 16);
                n1 = ldg_na(nb + 512 + lane * 16);
            }
            d[j] = dot8(a0, a1, p2);
            if (j < 7) { a0 = n0; a1 = n1; }
        }
    }

    // ---- fold-butterfly: 8 candidates reduced with 9 SHFLs ----
    {
        float e[4], f[2], g;
        #pragma unroll
        for (int k = 0; k < 4; k++) {
            float v = (lane & 1) ? d[2*k+1] : d[2*k];
            float w = (lane & 1) ? d[2*k]   : d[2*k+1];
            e[k] = v + __shfl_xor_sync(FULL, w, 1);
        }
        #pragma unroll
        for (int k = 0; k < 2; k++) {
            float v = (lane & 2) ? e[2*k+1] : e[2*k];
            float w = (lane & 2) ? e[2*k]   : e[2*k+1];
            f[k] = v + __shfl_xor_sync(FULL, w, 2);
        }
        {
            float v = (lane & 4) ? f[1] : f[0];
            float w = (lane & 4) ? f[0] : f[1];
            g = v + __shfl_xor_sync(FULL, w, 4);
        }
        g += __shfl_xor_sync(FULL, g, 8);
        g += __shfl_xor_sync(FULL, g, 16);
        if (lane < 8) sims[warp + 8 * lane] = g * 10.0f;
    }

    // tail candidate 64 (warp 0)
    if (warp == 0) {
        const char* eT = (const char*)g_enc + (size_t)sel[64] * 1024;
        uint4 t0 = ldg_na(eT + lane * 16);
        uint4 t1 = ldg_na(eT + 512 + lane * 16);
        float dt = dot8(t0, t1, p2);
        #pragma unroll
        for (int o = 16; o; o >>= 1) dt += __shfl_xor_sync(FULL, dt, o);
        if (lane == 0) sims[64] = dt * 10.0f;
    }
    __syncthreads();

    // ---- warp-parallel LSE / argmax (warp 0) ----
    if (warp == 0) {
        float v0 = sims[lane];
        float v1 = sims[lane + 32];
        float v2 = (lane == 0) ? sims[64] : -3.4e38f;
        float mx = fmaxf(fmaxf(v0, v1), v2);
        #pragma unroll
        for (int o = 16; o; o >>= 1) mx = fmaxf(mx, __shfl_xor_sync(FULL, mx, o));
        float s = expf(v0 - mx) + expf(v1 - mx) + ((lane == 0) ? expf(v2 - mx) : 0.0f);
        #pragma unroll
        for (int o = 16; o; o >>= 1) s += __shfl_xor_sync(FULL, s, o);
        if (lane == 0) {
            float s0 = sims[0];
            g_rowloss[m] = mx + logf(s) - s0;
            g_rowacc[m]  = (s0 >= mx) ? 1.0f : 0.0f;
        }
    }

    // ---- two-level arrival tree + fused deterministic final reduce ----
    __syncthreads();
    __threadfence();
    if (tid == 0) {
        bool l = false;
        if (atomicAdd(&g_cnt1[m >> 6], 1u) == 63u) {
            if (atomicAdd(&g_cnt2, 1u) == 63u) l = true;
        }
        last = l;
    }
    __syncthreads();
    if (!last) return;
    __threadfence();

    if (tid < 64) g_cnt1[tid] = 0u;        // self-reset for next replay
    if (tid == 64) g_cnt2 = 0u;

    float sl = 0.0f, sa = 0.0f;
    #pragma unroll
    for (int k = 0; k < M_PAIRS / 256; k++) {
        int i = k * 256 + tid;
        sl += g_rowloss[i];
        sa += g_rowacc[i];
    }
    __shared__ float bl[8], ba[8];
    #pragma unroll
    for (int o = 16; o; o >>= 1) {
        sl += __shfl_xor_sync(FULL, sl, o);
        sa += __shfl_xor_sync(FULL, sa, o);
    }
    if (lane == 0) { bl[warp] = sl; ba[warp] = sa; }
    __syncthreads();
    if (tid == 0) {
        float tl = 0.0f, ta = 0.0f;
        #pragma unroll
        for (int w = 0; w < 8; w++) { tl += bl[w]; ta += ba[w]; }
        out[0] = tl / (float)M_PAIRS;
        if (out_size > 1) out[1] = ta / (float)M_PAIRS;
    }
}

// ---------------- Launch ----------------------------------------------------
extern "C" void kernel_launch(void* const* d_in, const int* in_sizes, int n_in,
                              void* d_out, int out_size) {
    const float* pred = (const float*)d_in[0];
    const float* enc  = (const float*)d_in[1];
    const void*  mask = d_in[2];

    gather_norm_kernel<<<M_PAIRS / 8, 256>>>(pred, enc, mask);

    // sim_kernel launched with Programmatic Dependent Launch: dispatch overlaps
    // gather's tail; griddepcontrol.wait inside orders the data.
    cudaLaunchConfig_t cfg = {};
    cfg.gridDim  = dim3(M_PAIRS, 1, 1);
    cfg.blockDim = dim3(256, 1, 1);
    cudaLaunchAttribute attr[1];
    attr[0].id = cudaLaunchAttributeProgrammaticStreamSerialization;
    attr[0].val.programmaticStreamSerializationAllowed = 1;
    cfg.attrs = attr;
    cfg.numAttrs = 1;
    float* outp = (float*)d_out;
    cudaLaunchKernelEx(&cfg, sim_kernel, outp, out_size);
}